// round 2
// baseline (speedup 1.0000x reference)
#include <cuda_runtime.h>
#include <math.h>

#define BB 16
#define CC 256
#define HH 128
#define WW 128
#define HWp (HH*WW)          // 16384
#define HW4 (HWp/4)          // 4096

// Scratch (device globals — no allocations allowed)
__device__ float g_sf[BB*2*HWp];     // [B,2,H,W]  avg(ch0), max(ch1)
__device__ float g_h1[BB*16*HWp];    // [B,16,H,W]
__device__ float g_samp[BB*2*HWp];   // [B,2,H,W]
__device__ float g_w2eff[2*16*9];    // [2,16,3,3] channel-group-averaged w2
__device__ float g_b2eff[2];

// ---------------------------------------------------------------------------
// Kernel 1: channel reduce (avg + max over C=256). HBM-bound: 268 MB read.
// ---------------------------------------------------------------------------
__global__ void k_reduce(const float* __restrict__ x) {
    int idx = blockIdx.x * blockDim.x + threadIdx.x;   // 0..65535
    int b  = idx >> 12;            // / 4096
    int p4 = idx & 4095;
    const float4* xp = reinterpret_cast<const float4*>(x) + (size_t)b * CC * HW4 + p4;

    float4 s = make_float4(0.f, 0.f, 0.f, 0.f);
    float4 m = make_float4(-1e30f, -1e30f, -1e30f, -1e30f);
    #pragma unroll 8
    for (int c = 0; c < CC; ++c) {
        float4 v = __ldg(xp + (size_t)c * HW4);
        s.x += v.x; s.y += v.y; s.z += v.z; s.w += v.w;
        m.x = fmaxf(m.x, v.x); m.y = fmaxf(m.y, v.y);
        m.z = fmaxf(m.z, v.z); m.w = fmaxf(m.w, v.w);
    }
    const float inv = 1.0f / (float)CC;
    s.x *= inv; s.y *= inv; s.z *= inv; s.w *= inv;

    float4* o = reinterpret_cast<float4*>(g_sf);
    o[(size_t)b * 2 * HW4 + p4]       = s;   // avg  -> channel 0
    o[(size_t)b * 2 * HW4 + HW4 + p4] = m;   // max  -> channel 1
}

// ---------------------------------------------------------------------------
// Kernel 2: average w2/b2 over the 49-channel groups (conv linear => exact).
// ---------------------------------------------------------------------------
__global__ void k_w2eff(const float* __restrict__ w2, const float* __restrict__ b2) {
    int i = threadIdx.x;
    if (i < 288) {
        int d = i / 144;          // 0 or 1 (x / y offset group)
        int k = i % 144;          // [16,3,3] inner index
        float s = 0.f;
        for (int j = 0; j < 49; ++j) s += w2[(size_t)(d * 49 + j) * 144 + k];
        g_w2eff[i] = s * (1.0f / 49.0f);
    }
    if (i < 2) {
        float s = 0.f;
        for (int j = 0; j < 49; ++j) s += b2[i * 49 + j];
        g_b2eff[i] = s * (1.0f / 49.0f);
    }
}

// ---------------------------------------------------------------------------
// Kernel 3: conv3x3 (2->16) + BN(eval) + ReLU.
// ---------------------------------------------------------------------------
__global__ void k_conv1(const float* __restrict__ w1,
                        const float* __restrict__ gamma, const float* __restrict__ beta,
                        const float* __restrict__ mean,  const float* __restrict__ var) {
    __shared__ float ws[288];
    __shared__ float sc[16], bi[16];
    int t = threadIdx.x;
    for (int i = t; i < 288; i += blockDim.x) ws[i] = w1[i];   // FIXED: full fill
    if (t < 16) {
        float s = gamma[t] * rsqrtf(var[t] + 1e-5f);
        sc[t] = s;
        bi[t] = beta[t] - mean[t] * s;
    }
    __syncthreads();

    int idx = blockIdx.x * blockDim.x + t;      // 0..262143
    int b   = idx >> 14;
    int rem = idx & 16383;
    int y = rem >> 7, x = rem & 127;

    const float* sfb = g_sf + (size_t)b * 2 * HWp;
    float v[18];
    #pragma unroll
    for (int ic = 0; ic < 2; ++ic)
        #pragma unroll
        for (int kh = 0; kh < 3; ++kh)
            #pragma unroll
            for (int kw = 0; kw < 3; ++kw) {
                int yy = y + kh - 1, xx = x + kw - 1;
                float val = 0.f;
                if (yy >= 0 && yy < HH && xx >= 0 && xx < WW)
                    val = sfb[ic * HWp + yy * WW + xx];
                v[ic * 9 + kh * 3 + kw] = val;
            }

    float* hb = g_h1 + (size_t)b * 16 * HWp + rem;
    #pragma unroll
    for (int oc = 0; oc < 16; ++oc) {
        float acc = 0.f;
        #pragma unroll
        for (int k = 0; k < 18; ++k) acc = fmaf(v[k], ws[oc * 18 + k], acc);
        acc = fmaf(acc, sc[oc], bi[oc]);          // BN affine
        hb[oc * HWp] = fmaxf(acc, 0.f);           // ReLU
    }
}

// ---------------------------------------------------------------------------
// Kernel 4: conv3x3 (16->2, averaged weights) + bias, tanh*0.5, deformable
// grid, bilinear grid_sample of sf (align_corners=False, zero padding).
// ---------------------------------------------------------------------------
__global__ void k_off_sample() {
    __shared__ float ws[288];
    __shared__ float b2s[2];
    int t = threadIdx.x;
    for (int i = t; i < 288; i += blockDim.x) ws[i] = g_w2eff[i];  // FIXED: full fill
    if (t < 2)   b2s[t] = g_b2eff[t];
    __syncthreads();

    int idx = blockIdx.x * blockDim.x + t;
    int b   = idx >> 14;
    int rem = idx & 16383;
    int y = rem >> 7, x = rem & 127;

    const float* hb = g_h1 + (size_t)b * 16 * HWp;
    float accx = b2s[0], accy = b2s[1];
    #pragma unroll
    for (int kh = 0; kh < 3; ++kh) {
        int yy = y + kh - 1;
        #pragma unroll
        for (int kw = 0; kw < 3; ++kw) {
            int xx = x + kw - 1;
            if (yy >= 0 && yy < HH && xx >= 0 && xx < WW) {
                int pos = yy * WW + xx;
                int wo  = kh * 3 + kw;
                #pragma unroll
                for (int ic = 0; ic < 16; ++ic) {
                    float val = hb[ic * HWp + pos];
                    accx = fmaf(val, ws[ic * 9 + wo],        accx);
                    accy = fmaf(val, ws[144 + ic * 9 + wo],  accy);
                }
            }
        }
    }

    float tx = tanhf(accx) * 0.5f;
    float ty = tanhf(accy) * 0.5f;
    float gxv = fmaf((float)x, 2.0f / 127.0f, -1.0f) + tx;
    float gyv = fmaf((float)y, 2.0f / 127.0f, -1.0f) + ty;
    gxv = fminf(fmaxf(gxv, -1.f), 1.f);
    gyv = fminf(fmaxf(gyv, -1.f), 1.f);

    // unnormalize (align_corners=False)
    float ix = ((gxv + 1.0f) * (float)WW - 1.0f) * 0.5f;
    float iy = ((gyv + 1.0f) * (float)HH - 1.0f) * 0.5f;
    float x0f = floorf(ix), y0f = floorf(iy);
    int x0 = (int)x0f, y0 = (int)y0f;
    int x1 = x0 + 1,   y1 = y0 + 1;
    float wx1 = ix - x0f, wx0 = 1.0f - wx1;
    float wy1 = iy - y0f, wy0 = 1.0f - wy1;

    const float* s0 = g_sf + (size_t)b * 2 * HWp;  // ch0 (avg)
    const float* s1 = s0 + HWp;                    // ch1 (max)

    float w00 = wx0 * wy0, w10 = wx1 * wy0, w01 = wx0 * wy1, w11 = wx1 * wy1;
    bool vx0 = (x0 >= 0) & (x0 < WW), vx1 = (x1 >= 0) & (x1 < WW);
    bool vy0 = (y0 >= 0) & (y0 < HH), vy1 = (y1 >= 0) & (y1 < HH);

    float o0 = 0.f, o1 = 0.f;
    if (vy0 & vx0) { int p = y0 * WW + x0; o0 = fmaf(s0[p], w00, o0); o1 = fmaf(s1[p], w00, o1); }
    if (vy0 & vx1) { int p = y0 * WW + x1; o0 = fmaf(s0[p], w10, o0); o1 = fmaf(s1[p], w10, o1); }
    if (vy1 & vx0) { int p = y1 * WW + x0; o0 = fmaf(s0[p], w01, o0); o1 = fmaf(s1[p], w01, o1); }
    if (vy1 & vx1) { int p = y1 * WW + x1; o0 = fmaf(s0[p], w11, o0); o1 = fmaf(s1[p], w11, o1); }

    g_samp[(size_t)b * 2 * HWp + rem]       = o0;
    g_samp[(size_t)b * 2 * HWp + HWp + rem] = o1;
}

// ---------------------------------------------------------------------------
// Kernel 5: conv7x7 (2->1, pad 3) + sigmoid -> output [B,1,H,W]
// ---------------------------------------------------------------------------
__global__ void k_attn(const float* __restrict__ aw, float* __restrict__ out) {
    __shared__ float ws[98];
    int t = threadIdx.x;
    if (t < 98) ws[t] = aw[t];
    __syncthreads();

    int idx = blockIdx.x * blockDim.x + t;
    int b   = idx >> 14;
    int rem = idx & 16383;
    int y = rem >> 7, x = rem & 127;

    const float* sb = g_samp + (size_t)b * 2 * HWp;
    float acc = 0.f;
    #pragma unroll
    for (int kh = 0; kh < 7; ++kh) {
        int yy = y + kh - 3;
        if (yy < 0 || yy >= HH) continue;
        #pragma unroll
        for (int kw = 0; kw < 7; ++kw) {
            int xx = x + kw - 3;
            if (xx < 0 || xx >= WW) continue;
            int pos = yy * WW + xx;
            acc = fmaf(sb[pos],        ws[kh * 7 + kw],      acc);
            acc = fmaf(sb[HWp + pos],  ws[49 + kh * 7 + kw], acc);
        }
    }
    out[idx] = 1.0f / (1.0f + expf(-acc));
}

// ---------------------------------------------------------------------------
extern "C" void kernel_launch(void* const* d_in, const int* in_sizes, int n_in,
                              void* d_out, int out_size) {
    const float* x     = (const float*)d_in[0];
    const float* w1    = (const float*)d_in[1];
    const float* gamma = (const float*)d_in[2];
    const float* beta  = (const float*)d_in[3];
    const float* mean  = (const float*)d_in[4];
    const float* var   = (const float*)d_in[5];
    const float* w2    = (const float*)d_in[6];
    const float* b2    = (const float*)d_in[7];
    const float* aw    = (const float*)d_in[8];
    float* out = (float*)d_out;

    k_reduce<<<256, 256>>>(x);                       // 65536 threads
    k_w2eff<<<1, 512>>>(w2, b2);
    k_conv1<<<1024, 256>>>(w1, gamma, beta, mean, var);
    k_off_sample<<<1024, 256>>>();
    k_attn<<<1024, 256>>>(aw, out);
}